// round 17
// baseline (speedup 1.0000x reference)
#include <cuda_runtime.h>
#include <cuda_fp16.h>
#include <cstdint>

#define NN 50000
#define NE 800000
#define IND 2613
#define IND16 2624                    // IND padded to 16
#define HD  256
#define NROWS_H1 25088                // 196 tiles * 128
#define BM 128
#define BNT 128

// ---------------- scratch (static device memory; no allocs) ----------------
__device__ __align__(256) __half g_a16[(size_t)NN * IND16];  // fp16 X, padded
__device__ __align__(256) __half g_h16[(size_t)NN * HD];
__device__ __align__(256) __half g_x16[(size_t)NN * HD];
__device__ __align__(256) __half g_w16[256 * IND16 + 4 * 256 * 256];
__device__ float g_dinv[NN];
__device__ int   g_deg[NN];
__device__ int   g_cursor[NN];
__device__ int   g_rowptr[NN + 1];
__device__ int   g_srcs[NE];

#define W0_OFF 0
#define W1_OFF (256 * IND16)
#define W2_OFF (W1_OFF + 256 * 256)
#define W3_OFF (W2_OFF + 256 * 256)
#define W4_OFF (W3_OFF + 256 * 256)

// ============================ PTX helpers ============================
__device__ __forceinline__ uint32_t smem_u32(const void* p) {
    uint32_t a;
    asm("{ .reg .u64 t; cvta.to.shared.u64 t, %1; cvt.u32.u64 %0, t; }" : "=r"(a) : "l"(p));
    return a;
}
__device__ __forceinline__ void ldmx4(uint32_t* r, uint32_t addr) {
    asm volatile("ldmatrix.sync.aligned.m8n8.x4.shared.b16 {%0,%1,%2,%3}, [%4];"
                 : "=r"(r[0]), "=r"(r[1]), "=r"(r[2]), "=r"(r[3]) : "r"(addr));
}
__device__ __forceinline__ void mma_f16(float* c, const uint32_t* a, const uint32_t* b) {
    asm volatile("mma.sync.aligned.m16n8k16.row.col.f32.f16.f16.f32 "
                 "{%0,%1,%2,%3}, {%4,%5,%6,%7}, {%8,%9}, {%0,%1,%2,%3};"
                 : "+f"(c[0]), "+f"(c[1]), "+f"(c[2]), "+f"(c[3])
                 : "r"(a[0]), "r"(a[1]), "r"(a[2]), "r"(a[3]), "r"(b[0]), "r"(b[1]));
}
__device__ __forceinline__ void cpa16(uint32_t dst, const void* src, uint32_t nbytes) {
    asm volatile("cp.async.cg.shared.global [%0], [%1], 16, %2;"
                 :: "r"(dst), "l"(src), "r"(nbytes) : "memory");
}
#define CP_COMMIT() asm volatile("cp.async.commit_group;" ::: "memory")
template <int N>
__device__ __forceinline__ void cp_wait() {
    asm volatile("cp.async.wait_group %0;" :: "n"(N) : "memory");
}

// ============================ converts ============================
__global__ void k_wcvt(const float* __restrict__ W, __half* __restrict__ out,
                       int K, int K16) {
    int i = blockIdx.x * 256 + threadIdx.x;
    if (i >= 256 * K16) return;
    int r = i / K16, c = i - r * K16;
    out[i] = (c < K) ? __float2half_rn(__ldg(W + (size_t)r * K + c)) : __half(0.f);
}
__global__ void k_xcvt(const float* __restrict__ x, __half* __restrict__ out,
                       int r0, int r1) {
    const int CP = IND16 / 2;
    long i = (long)blockIdx.x * 256 + threadIdx.x;
    long total = (long)(r1 - r0) * CP;
    if (i >= total) return;
    int r  = (int)(i / CP);
    int cp = (int)(i - (long)r * CP);
    int row = r0 + r;
    int c = cp * 2;
    const float* px = x + (size_t)row * IND;
    float f0 = (c     < IND) ? __ldg(px + c)     : 0.f;
    float f1 = (c + 1 < IND) ? __ldg(px + c + 1) : 0.f;
    ((__half2*)out)[(size_t)row * CP + cp] = __floats2half2_rn(f0, f1);
}

// ============================ CSR build ============================
__global__ void k_zero() {
    int i = blockIdx.x * blockDim.x + threadIdx.x;
    if (i < NN) { g_deg[i] = 0; g_cursor[i] = 0; }
}
__global__ void k_histo(const int* __restrict__ dst) {
    int e = blockIdx.x * blockDim.x + threadIdx.x;
    if (e < NE) atomicAdd(&g_deg[dst[e]], 1);
}
#define SCH 49
__global__ void __launch_bounds__(1024) k_scan() {
    __shared__ int wsum[32];
    int tid = threadIdx.x;
    int lane = tid & 31, w = tid >> 5;
    int base = tid * SCH;

    int sum = 0;
    for (int j = 0; j < SCH; j++) {
        int i = base + j;
        int v = (i < NN) ? g_deg[i] : 0;
        if (i < NN) g_dinv[i] = rsqrtf((float)(v + 1));
        sum += v;
    }
    int x = sum;
#pragma unroll
    for (int o = 1; o < 32; o <<= 1) {
        int t = __shfl_up_sync(0xffffffffu, x, o);
        if (lane >= o) x += t;
    }
    if (lane == 31) wsum[w] = x;
    __syncthreads();
    if (w == 0) {
        int y = wsum[lane];
#pragma unroll
        for (int o = 1; o < 32; o <<= 1) {
            int t = __shfl_up_sync(0xffffffffu, y, o);
            if (lane >= o) y += t;
        }
        wsum[lane] = y;
    }
    __syncthreads();
    int excl = x - sum + (w > 0 ? wsum[w - 1] : 0);

    int run = excl;
    for (int j = 0; j < SCH; j++) {
        int i = base + j;
        if (i < NN) {
            g_rowptr[i] = run;
            run += g_deg[i];
        }
    }
    if (tid == 1023) g_rowptr[NN] = excl + sum;
}
__global__ void k_scatter(const int* __restrict__ src, const int* __restrict__ dst) {
    int e = blockIdx.x * blockDim.x + threadIdx.x;
    if (e < NE) {
        int d = dst[e];
        int p = g_rowptr[d] + atomicAdd(&g_cursor[d], 1);
        g_srcs[p] = src[e];
    }
}

// ============================ fp16 GEMM ============================
// CTA 128x128, 256 thr, 8 warps (4M x 2N) of 32x64, 2 CTAs/SM.
// All-cp.async fill, BK=64, 3-stage ring, one syncthreads per stage.
// EPI 0: C = acc * dinv[row], fp16 out (GCN layers)
// EPI 1: C = elu(acc + bias), fp16 out   EPI 2: C = acc + bias, fp32 out
template <int EPI, bool OUTH>
__global__ void __launch_bounds__(256, 2)
k_tgemm(const __half* __restrict__ A16, const __half* __restrict__ B16,
        const float* __restrict__ bias, void* __restrict__ Cv,
        int M, int K16, int yoff)
{
    constexpr int BKT = 64, NSTGT = 3;
    constexpr int SROWT = BKT * 2 + 16;          // 144
    constexpr int A_OFFT = 0;
    constexpr int B_OFFT = 128 * SROWT;
    constexpr int STGB = 2 * 128 * SROWT;
    constexpr int CPR = BKT / 8;
    constexpr int NCH = (128 * CPR) / 256;
    constexpr int SS = BKT / 16;

    extern __shared__ char sm[];
    const uint32_t sb = smem_u32(sm);
    const int tid  = threadIdx.x;
    const int lane = tid & 31;
    const int wid  = tid >> 5;
    const int wm   = wid >> 1;
    const int wn   = wid & 1;
    const int bm   = (blockIdx.y + yoff) * BM;
    const int bn   = blockIdx.x * BNT;

    const uint32_t a_lrow = (uint32_t)(lane & 15);
    const uint32_t a_lkh  = (uint32_t)((lane >> 4) << 4);
    const uint32_t b_lrow = (uint32_t)((lane & 7) + ((lane >> 4) << 3));
    const uint32_t b_lkh  = (uint32_t)(((lane >> 3) & 1) << 4);

    float acc[2][8][4];
#pragma unroll
    for (int m = 0; m < 2; m++)
#pragma unroll
        for (int n = 0; n < 8; n++)
#pragma unroll
            for (int q = 0; q < 4; q++) acc[m][n][q] = 0.f;

    const int nt = K16 / BKT;

    auto cp_issue = [&](int kt) {
        const uint32_t stg = sb + (uint32_t)(kt % NSTGT) * STGB;
        const int k0 = kt * BKT;
#pragma unroll
        for (int i = 0; i < NCH; i++) {
            int id  = tid + i * 256;
            int row = id / CPR;
            int c8  = (id % CPR) * 8;
            int brw = bn + row;
            cpa16(stg + B_OFFT + (uint32_t)(row * SROWT + c8 * 2),
                  B16 + (size_t)brw * K16 + k0 + c8, 16u);
            int gr = bm + row;
            uint32_t nb = (gr < M) ? 16u : 0u;
            int grc = (gr < M) ? gr : 0;
            cpa16(stg + A_OFFT + (uint32_t)(row * SROWT + c8 * 2),
                  A16 + (size_t)grc * K16 + k0 + c8, nb);
        }
    };

#pragma unroll
    for (int s = 0; s < NSTGT - 1; s++) {
        if (s < nt) cp_issue(s);
        CP_COMMIT();
    }

    for (int kt = 0; kt < nt; kt++) {
        const uint32_t stg = (uint32_t)(kt % NSTGT) * STGB;

        cp_wait<NSTGT - 2>();
        __syncthreads();

        if (kt + NSTGT - 1 < nt) cp_issue(kt + NSTGT - 1);
        CP_COMMIT();

#pragma unroll
        for (int s = 0; s < SS; s++) {
            uint32_t a[2][4];
#pragma unroll
            for (int mt = 0; mt < 2; mt++) {
                uint32_t rowb = (uint32_t)(wm * 32 + mt * 16) + a_lrow;
                ldmx4(a[mt], sb + stg + A_OFFT + rowb * SROWT + s * 32 + a_lkh);
            }
#pragma unroll
            for (int ng = 0; ng < 4; ng++) {
                uint32_t bh[4];
                uint32_t nb = (uint32_t)(wn * 64 + ng * 16) + b_lrow;
                ldmx4(bh, sb + stg + B_OFFT + nb * SROWT + s * 32 + b_lkh);
#pragma unroll
                for (int mt = 0; mt < 2; mt++) {
                    mma_f16(acc[mt][ng * 2 + 0], a[mt], &bh[0]);
                    mma_f16(acc[mt][ng * 2 + 1], a[mt], &bh[2]);
                }
            }
        }
    }

    // ---- epilogue (C row stride = 256) ----
#pragma unroll
    for (int mt = 0; mt < 2; mt++) {
        int r0 = bm + wm * 32 + mt * 16 + (lane >> 2);
        int r1 = r0 + 8;
        float dv0 = 0.f, dv1 = 0.f;
        if (EPI == 0) {
            if (r0 < M) dv0 = __ldg(&g_dinv[r0]);
            if (r1 < M) dv1 = __ldg(&g_dinv[r1]);
        }
#pragma unroll
        for (int n = 0; n < 8; n++) {
            int cidx = bn + wn * 64 + n * 8 + (lane & 3) * 2;
            float b0 = 0.f, b1 = 0.f;
            if (EPI != 0) { b0 = __ldg(bias + cidx); b1 = __ldg(bias + cidx + 1); }
            float* c = acc[mt][n];
            float v0 = c[0], v1 = c[1], v2 = c[2], v3 = c[3];
            if (EPI == 0) {
                v0 *= dv0; v1 *= dv0; v2 *= dv1; v3 *= dv1;
            } else {
                v0 += b0; v1 += b1; v2 += b0; v3 += b1;
                if (EPI == 1) {
                    v0 = (v0 > 0.f) ? v0 : expm1f(v0);
                    v1 = (v1 > 0.f) ? v1 : expm1f(v1);
                    v2 = (v2 > 0.f) ? v2 : expm1f(v2);
                    v3 = (v3 > 0.f) ? v3 : expm1f(v3);
                }
            }
            if (OUTH) {
                __half* C = (__half*)Cv;
                if (r0 < M) *(__half2*)(C + (size_t)r0 * HD + cidx) = __floats2half2_rn(v0, v1);
                if (r1 < M) *(__half2*)(C + (size_t)r1 * HD + cidx) = __floats2half2_rn(v2, v3);
            } else {
                float* C = (float*)Cv;
                if (r0 < M) *(float2*)(C + (size_t)r0 * HD + cidx) = make_float2(v0, v1);
                if (r1 < M) *(float2*)(C + (size_t)r1 * HD + cidx) = make_float2(v2, v3);
            }
        }
    }
}

// ============================ aggregation ============================
// hs rows are pre-scaled by dinv[row] in the GEMM epilogue.
// out[v] = l2norm( relu( dinv[v]*(sum_{u->v} hs[u] + hs[v]) + bias ) )
// 2 nodes per 256-thread block; per-half named barriers.
__global__ void __launch_bounds__(256)
k_agg(const __half* __restrict__ hs, const float* __restrict__ bias,
      __half* __restrict__ outx)
{
    const int half = threadIdx.x >> 7;            // 0/1
    const int j    = threadIdx.x & 127;
    const int v    = blockIdx.x * 2 + half;
    if (v >= NN) return;
    const __half2* H = (const __half2*)hs;

    float2 fself = __half22float2(H[(size_t)v * 128 + j]);
    float s0 = fself.x, s1 = fself.y;

    int beg = __ldg(&g_rowptr[v]), end = __ldg(&g_rowptr[v + 1]);
    int e = beg;
    for (; e + 4 <= end; e += 4) {
        int u0 = __ldg(&g_srcs[e]);
        int u1 = __ldg(&g_srcs[e + 1]);
        int u2 = __ldg(&g_srcs[e + 2]);
        int u3 = __ldg(&g_srcs[e + 3]);
        float2 g0 = __half22float2(H[(size_t)u0 * 128 + j]);
        float2 g1 = __half22float2(H[(size_t)u1 * 128 + j]);
        float2 g2 = __half22float2(H[(size_t)u2 * 128 + j]);
        float2 g3 = __half22float2(H[(size_t)u3 * 128 + j]);
        s0 += g0.x + g1.x + g2.x + g3.x;
        s1 += g0.y + g1.y + g2.y + g3.y;
    }
    for (; e < end; e++) {
        int u = __ldg(&g_srcs[e]);
        float2 fu = __half22float2(H[(size_t)u * 128 + j]);
        s0 += fu.x;
        s1 += fu.y;
    }
    float dv = __ldg(&g_dinv[v]);
    float2 bb = __ldg((const float2*)bias + j);
    float v0 = fmaxf(fmaf(dv, s0, bb.x), 0.f);
    float v1 = fmaxf(fmaf(dv, s1, bb.y), 0.f);

    // per-half reduction: 4 warps each
    __shared__ float red[8];
    float ss = v0 * v0 + v1 * v1;
#pragma unroll
    for (int o = 16; o; o >>= 1) ss += __shfl_xor_sync(0xffffffffu, ss, o);
    const int wid = threadIdx.x >> 5;             // 0..7
    if ((threadIdx.x & 31) == 0) red[wid] = ss;
    asm volatile("bar.sync %0, %1;" :: "r"(half + 1), "r"(128) : "memory");
    float tot = red[half * 4] + red[half * 4 + 1] +
                red[half * 4 + 2] + red[half * 4 + 3];
    float scale = 1.f / fmaxf(sqrtf(tot), 1e-12f);
    ((__half2*)outx)[(size_t)v * 128 + j] = __floats2half2_rn(v0 * scale, v1 * scale);
}

// ============================ launch ============================
#define SM_F16 (3 * (2 * 128 * 144))  // 110592

extern "C" void kernel_launch(void* const* d_in, const int* in_sizes, int n_in,
                              void* d_out, int out_size)
{
    const float* x     = (const float*)d_in[0];
    const int*   edges = (const int*)  d_in[1];
    const float* Wg0   = (const float*)d_in[2];
    const float* bg0   = (const float*)d_in[3];
    const float* Wg1   = (const float*)d_in[4];
    const float* bg1   = (const float*)d_in[5];
    const float* Wg2   = (const float*)d_in[6];
    const float* bg2   = (const float*)d_in[7];
    const float* W1    = (const float*)d_in[8];
    const float* b1    = (const float*)d_in[9];
    const float* W2    = (const float*)d_in[10];
    const float* b2    = (const float*)d_in[11];
    float* out = (float*)d_out;

    const int* src = edges;
    const int* dst = edges + NE;

    __half *ap, *hp, *xp, *wp;
    cudaGetSymbolAddress((void**)&ap, g_a16);
    cudaGetSymbolAddress((void**)&hp, g_h16);
    cudaGetSymbolAddress((void**)&xp, g_x16);
    cudaGetSymbolAddress((void**)&wp, g_w16);

    cudaFuncSetAttribute((const void*)k_tgemm<0,true>,  cudaFuncAttributeMaxDynamicSharedMemorySize, SM_F16);
    cudaFuncSetAttribute((const void*)k_tgemm<1,true>,  cudaFuncAttributeMaxDynamicSharedMemorySize, SM_F16);
    cudaFuncSetAttribute((const void*)k_tgemm<2,false>, cudaFuncAttributeMaxDynamicSharedMemorySize, SM_F16);

    static cudaStream_t s2 = nullptr;
    static cudaEvent_t evA = nullptr, ev1 = nullptr, evScan = nullptr, evB = nullptr;
    if (s2 == nullptr) {
        cudaStreamCreateWithFlags(&s2, cudaStreamNonBlocking);
        cudaEventCreateWithFlags(&evA, cudaEventDisableTiming);
        cudaEventCreateWithFlags(&ev1, cudaEventDisableTiming);
        cudaEventCreateWithFlags(&evScan, cudaEventDisableTiming);
        cudaEventCreateWithFlags(&evB, cudaEventDisableTiming);
    }

    const int CP = IND16 / 2;
    const long xe1 = (long)NROWS_H1 * CP;
    const long xe2 = (long)(NN - NROWS_H1) * CP;
    const dim3 grd_h1(2, NROWS_H1 / BM);                    // (2,196)
    const dim3 grd_h2(2, (NN - NROWS_H1 + BM - 1) / BM);    // (2,195)
    const dim3 grd(2, (NN + BM - 1) / BM);                  // (2,391)

    // ---- fork: s2 joins capture via evA BEFORE any s2 launch ----
    cudaEventRecord(evA, 0);
    cudaStreamWaitEvent(s2, evA, 0);

    // side stream: CSR (scan -> dinv for GEMM0 epilogue) + small wcvts
    k_zero   <<<(NN + 255) / 256, 256, 0, s2>>>();
    k_histo  <<<(NE + 255) / 256, 256, 0, s2>>>(dst);
    k_scan   <<<1, 1024, 0, s2>>>();
    cudaEventRecord(evScan, s2);
    k_scatter<<<(NE + 255) / 256, 256, 0, s2>>>(src, dst);
    k_wcvt<<<(256 * 256 + 255) / 256, 256, 0, s2>>>(Wg1, wp + W1_OFF, HD, HD);
    k_wcvt<<<(256 * 256 + 255) / 256, 256, 0, s2>>>(Wg2, wp + W2_OFF, HD, HD);
    k_wcvt<<<(256 * 256 + 255) / 256, 256, 0, s2>>>(W1,  wp + W3_OFF, HD, HD);
    k_wcvt<<<(256 * 256 + 255) / 256, 256, 0, s2>>>(W2,  wp + W4_OFF, HD, HD);

    // main: W0 convert, X convert halves, GEMM0 half2
    k_wcvt<<<(256 * IND16 + 255) / 256, 256>>>(Wg0, wp + W0_OFF, IND, IND16);
    k_xcvt<<<(int)((xe1 + 255) / 256), 256>>>(x, ap, 0, NROWS_H1);
    cudaEventRecord(ev1, 0);                 // W0 + X(h1) ready
    k_xcvt<<<(int)((xe2 + 255) / 256), 256>>>(x, ap, NROWS_H1, NN);
    cudaStreamWaitEvent(0, evScan, 0);       // dinv ready (captured event)
    k_tgemm<0,true><<<grd_h2, 256, SM_F16>>>(ap, wp + W0_OFF, nullptr, hp, NN, IND16, NROWS_H1 / BM);

    // side: GEMM0 half1 (overlaps xcvt h2 + GEMM0 h2); needs dinv (same stream as scan)
    cudaStreamWaitEvent(s2, ev1, 0);
    k_tgemm<0,true><<<grd_h1, 256, SM_F16, s2>>>(ap, wp + W0_OFF, nullptr, hp, NN, IND16, 0);
    cudaEventRecord(evB, s2);

    cudaStreamWaitEvent(0, evB, 0);
    k_agg<<<NN / 2, 256>>>(hp, bg0, xp);
    // GCN layer 1
    k_tgemm<0,true><<<grd, 256, SM_F16>>>(xp, wp + W1_OFF, nullptr, hp, NN, HD, 0);
    k_agg<<<NN / 2, 256>>>(hp, bg1, xp);
    // GCN layer 2
    k_tgemm<0,true><<<grd, 256, SM_F16>>>(xp, wp + W2_OFF, nullptr, hp, NN, HD, 0);
    k_agg<<<NN / 2, 256>>>(hp, bg2, xp);
    // MLP
    k_tgemm<1,true><<<grd, 256, SM_F16>>>(xp, wp + W3_OFF, b1, hp,  NN, HD, 0);
    k_tgemm<2,false><<<grd, 256, SM_F16>>>(hp, wp + W4_OFF, b2, out, NN, HD, 0);
}